// round 4
// baseline (speedup 1.0000x reference)
#include <cuda_runtime.h>
#include <cuda_bf16.h>

#define NU 8
#define MA 1024
#define NPAIRS 28              // NU*(NU-1)/2
#define IH 2                   // i halves per pair (512 i each)
#define JC 64                  // j chunks per unit
#define JT 16                  // j tile size
#define THREADS 128
#define IPT 4                  // i points per thread (128*4 = 512)
#define PAIR_BLOCKS (NPAIRS * IH * JC)   // 3584
#define TOTAL_BLOCKS (PAIR_BLOCKS + NU)  // +8 L1 blocks

__device__ float g_acc;        // single accumulator; reset by finalizer
__device__ unsigned g_ticket;  // arrival counter; reset by finalizer

__device__ __forceinline__ unsigned long long pk2(float a, float b) {
    unsigned long long r;
    asm("mov.b64 %0, {%1, %2};" : "=l"(r) : "f"(a), "f"(b));
    return r;
}
__device__ __forceinline__ void upk2(float& a, float& b, unsigned long long v) {
    asm("mov.b64 {%0, %1}, %2;" : "=f"(a), "=f"(b) : "l"(v));
}
__device__ __forceinline__ unsigned long long fma2(unsigned long long a, unsigned long long b, unsigned long long c) {
    unsigned long long d;
    asm("fma.rn.f32x2 %0, %1, %2, %3;" : "=l"(d) : "l"(a), "l"(b), "l"(c));
    return d;
}
__device__ __forceinline__ float ex2f(float x) {
    float r;
    asm("ex2.approx.f32 %0, %1;" : "=r"(*(unsigned*)&r) : "r"(*(unsigned*)&x));
    return r;
}

// Build rotation matrices + positions into shared (threads 0..7, one unit each)
__device__ __forceinline__ void build_R(float (*Rsh)[12],
                                        const float* __restrict__ pos,
                                        const float* __restrict__ euler,
                                        int tid) {
    if (tid < NU) {
        float phi = euler[tid * 3 + 0];
        float the = euler[tid * 3 + 1];
        float psi = euler[tid * 3 + 2];
        float cp = __cosf(phi), sp = __sinf(phi);
        float ct = __cosf(the), st = __sinf(the);
        float cs = __cosf(psi), ss = __sinf(psi);
        // R = Rz(psi) @ Ry(theta) @ Rx(phi)
        Rsh[tid][0] = cs * ct;
        Rsh[tid][1] = -ss * cp + cs * st * sp;
        Rsh[tid][2] = ss * sp + cs * st * cp;
        Rsh[tid][3] = ss * ct;
        Rsh[tid][4] = cs * cp + ss * st * sp;
        Rsh[tid][5] = -cs * sp + ss * st * cp;
        Rsh[tid][6] = -st;
        Rsh[tid][7] = ct * sp;
        Rsh[tid][8] = ct * cp;
        Rsh[tid][9]  = pos[tid * 3 + 0];
        Rsh[tid][10] = pos[tid * 3 + 1];
        Rsh[tid][11] = pos[tid * 3 + 2];
    }
}

// Transform atom m with unit u's rotation+position
__device__ __forceinline__ void xform(const float (*Rsh)[12],
                                      const float* __restrict__ coords,
                                      int u, int m,
                                      float& px, float& py, float& pz, float& sq) {
    float cx = coords[m * 3 + 0];
    float cy = coords[m * 3 + 1];
    float cz = coords[m * 3 + 2];
    const float* R = Rsh[u];
    px = fmaf(R[0], cx, fmaf(R[1], cy, fmaf(R[2], cz, R[9])));
    py = fmaf(R[3], cx, fmaf(R[4], cy, fmaf(R[5], cz, R[10])));
    pz = fmaf(R[6], cx, fmaf(R[7], cy, fmaf(R[8], cz, R[11])));
    sq = px * px + py * py + pz * pz;
}

// ---------------------------------------------------------------------------
// Single fused kernel, 128-thread blocks.
// Blocks [0, 3584): pair tiles. b: jc = b&63, ih = (b>>6)&1, p = b>>7.
//   512 i (4/thread) x 16 j per block.
// Blocks [3584, 3592): L1 per unit (+ L_com in the first one).
// pen = exp2(c_i) * exp2(c_j + dot(Pi', Pj')),  P' = S*p, S^2 = 2*log2e,
// c = log2e*(0.5 - |p|^2)   =>  product = exp(1 - d2)
// ---------------------------------------------------------------------------
__global__ void __launch_bounds__(THREADS, 8) fused_kernel(const float* __restrict__ pos,
                                                           const float* __restrict__ euler,
                                                           const float* __restrict__ coords,
                                                           float* __restrict__ out) {
    __shared__ float Rsh[NU][12];
    __shared__ __align__(16) float sj[4][JT];   // SoA j tile: X, Y, Z, c
    __shared__ float wsum[THREADS / 32];

    const float LOG2E = 1.4426950408889634f;
    const float S = 1.6986436005760381f;        // sqrt(2*log2e)
    int tid = threadIdx.x;
    int b = blockIdx.x;

    build_R(Rsh, pos, euler, tid);
    __syncthreads();

    float blockContrib = 0.0f;   // value thread 0 will atomicAdd

    if (b < PAIR_BLOCKS) {
        int jc = b & 63;
        int ih = (b >> 6) & 1;
        int p  = b >> 7;
        // pair index -> (u, v), u < v
        int rem = p, u = 0, row = NU - 1;
        while (rem >= row) { rem -= row; row--; u++; }
        int v = u + 1 + rem;

        // Stage j tile (unit v), 16 threads
        if (tid < JT) {
            float px, py, pz, sq;
            xform(Rsh, coords, v, jc * JT + tid, px, py, pz, sq);
            sj[0][tid] = S * px;
            sj[1][tid] = S * py;
            sj[2][tid] = S * pz;
            sj[3][tid] = LOG2E * (0.5f - sq);
        }

        // i points (unit u): 4 per thread
        float px0, py0, pz0, sq0, px1, py1, pz1, sq1;
        float px2, py2, pz2, sq2, px3, py3, pz3, sq3;
        int im = u * MA + ih * 512 + tid;
        xform(Rsh, coords, u, ih * 512 + tid,           px0, py0, pz0, sq0);
        xform(Rsh, coords, u, ih * 512 + tid + 128,     px1, py1, pz1, sq1);
        xform(Rsh, coords, u, ih * 512 + tid + 256,     px2, py2, pz2, sq2);
        xform(Rsh, coords, u, ih * 512 + tid + 384,     px3, py3, pz3, sq3);
        (void)im;

        unsigned long long DX0 = pk2(S * px0, S * px0), DY0 = pk2(S * py0, S * py0), DZ0 = pk2(S * pz0, S * pz0);
        unsigned long long DX1 = pk2(S * px1, S * px1), DY1 = pk2(S * py1, S * py1), DZ1 = pk2(S * pz1, S * pz1);
        unsigned long long DX2 = pk2(S * px2, S * px2), DY2 = pk2(S * py2, S * py2), DZ2 = pk2(S * pz2, S * pz2);
        unsigned long long DX3 = pk2(S * px3, S * px3), DY3 = pk2(S * py3, S * py3), DZ3 = pk2(S * pz3, S * pz3);
        float e0 = ex2f(LOG2E * (0.5f - sq0));
        float e1 = ex2f(LOG2E * (0.5f - sq1));
        float e2 = ex2f(LOG2E * (0.5f - sq2));
        float e3 = ex2f(LOG2E * (0.5f - sq3));

        __syncthreads();

        const unsigned long long* xp = reinterpret_cast<const unsigned long long*>(sj[0]);
        const unsigned long long* yp = reinterpret_cast<const unsigned long long*>(sj[1]);
        const unsigned long long* zp = reinterpret_cast<const unsigned long long*>(sj[2]);
        const unsigned long long* cp = reinterpret_cast<const unsigned long long*>(sj[3]);

        // raw accumulators (e_i applied after the loop)
        float s0 = 0.f, s1 = 0.f, s2 = 0.f, s3 = 0.f;

#pragma unroll
        for (int t = 0; t < JT / 2; t++) {
            unsigned long long XJ = xp[t];
            unsigned long long YJ = yp[t];
            unsigned long long ZJ = zp[t];
            unsigned long long CJ = cp[t];
            float lo, hi;

            unsigned long long t0 = fma2(DX0, XJ, CJ);
            t0 = fma2(DY0, YJ, t0);
            t0 = fma2(DZ0, ZJ, t0);
            upk2(lo, hi, t0);
            s0 += ex2f(lo);
            s0 += ex2f(hi);

            unsigned long long t1 = fma2(DX1, XJ, CJ);
            t1 = fma2(DY1, YJ, t1);
            t1 = fma2(DZ1, ZJ, t1);
            upk2(lo, hi, t1);
            s1 += ex2f(lo);
            s1 += ex2f(hi);

            unsigned long long t2 = fma2(DX2, XJ, CJ);
            t2 = fma2(DY2, YJ, t2);
            t2 = fma2(DZ2, ZJ, t2);
            upk2(lo, hi, t2);
            s2 += ex2f(lo);
            s2 += ex2f(hi);

            unsigned long long t3 = fma2(DX3, XJ, CJ);
            t3 = fma2(DY3, YJ, t3);
            t3 = fma2(DZ3, ZJ, t3);
            upk2(lo, hi, t3);
            s3 += ex2f(lo);
            s3 += ex2f(hi);
        }

        float s = fmaf(e0, s0, fmaf(e1, s1, fmaf(e2, s2, e3 * s3)));
#pragma unroll
        for (int o = 16; o > 0; o >>= 1)
            s += __shfl_xor_sync(0xFFFFFFFFu, s, o);
        if ((tid & 31) == 0) wsum[tid >> 5] = s;
        __syncthreads();
        if (tid == 0) {
            float bs = 0.f;
#pragma unroll
            for (int w = 0; w < THREADS / 32; w++) bs += wsum[w];
            blockContrib = 0.5f * bs;      // LAMBDA1 = 0.5
        }
    } else {
        // L1 block for unit u (+ L_com in the u==0 block)
        int u = b - PAIR_BLOCKS;
        float l1 = 0.0f;
#pragma unroll
        for (int k = 0; k < MA / THREADS; k++) {
            float px, py, pz, sq;
            xform(Rsh, coords, u, k * THREADS + tid, px, py, pz, sq);
            l1 += sq;
        }
#pragma unroll
        for (int o = 16; o > 0; o >>= 1)
            l1 += __shfl_xor_sync(0xFFFFFFFFu, l1, o);
        if ((tid & 31) == 0) wsum[tid >> 5] = l1;
        __syncthreads();
        if (tid == 0) {
            float bs = 0.f;
#pragma unroll
            for (int w = 0; w < THREADS / 32; w++) bs += wsum[w];
            blockContrib = bs / (float)NU;      // contribution to L1 mean
            if (u == 0) {
                float ccx = 0.f, ccy = 0.f, ccz = 0.f;
#pragma unroll
                for (int uu = 0; uu < NU; uu++) {
                    ccx += Rsh[uu][9]; ccy += Rsh[uu][10]; ccz += Rsh[uu][11];
                }
                blockContrib += ccx * ccx + ccy * ccy + ccz * ccz;   // ALPHA = 1
            }
        }
    }

    // Accumulate + ticket finalize (thread 0 of every block)
    if (tid == 0) {
        atomicAdd(&g_acc, blockContrib);
        __threadfence();
        unsigned old = atomicAdd(&g_ticket, 1u);
        if (old == TOTAL_BLOCKS - 1) {
            __threadfence();
            float total = *((volatile float*)&g_acc);
            out[0] = total;
            g_acc = 0.0f;        // reset for next graph replay
            g_ticket = 0u;
        }
    }
}

extern "C" void kernel_launch(void* const* d_in, const int* in_sizes, int n_in,
                              void* d_out, int out_size) {
    const float* positions = (const float*)d_in[0];
    const float* euler     = (const float*)d_in[1];
    const float* coords    = (const float*)d_in[2];
    float* out = (float*)d_out;

    fused_kernel<<<TOTAL_BLOCKS, THREADS>>>(positions, euler, coords, out);
}